// round 4
// baseline (speedup 1.0000x reference)
#include <cuda_runtime.h>
#include <stdint.h>

#define NCOLS   24576
#define THREADS 512
#define NWARPS  (THREADS / 32)
#define EPT     (NCOLS / (THREADS * 4))   // 12 uint4 per thread
#define HBINS   4096
#define TIE_CAP 8192
// smem words: keys + hist + warp-totals + select-out(4) + vars(4)
#define SMEM_WORDS (NCOLS + HBINS + NWARPS + 4 + 4)
#define SMEM_BYTES (SMEM_WORDS * 4)

// ---- order-preserving float<->key transform (descending-friendly: bigger key = bigger float)
__device__ __forceinline__ uint32_t f2key(float f) {
    uint32_t b = __float_as_uint(f);
    return (b & 0x80000000u) ? ~b : (b | 0x80000000u);
}
__device__ __forceinline__ float key2f(uint32_t k) {
    uint32_t b = (k & 0x80000000u) ? (k ^ 0x80000000u) : ~k;
    return __uint_as_float(b);
}

// Block-wide suffix select over histogram h: each thread owns G consecutive bins
// [t*G, t*G+G). Finds bin b = max{b : count(bins >= b) >= rank}, writes
// s_sel[0]=bin, s_sel[1]=rank-within-bin (1-based), s_sel[2]=bin count.
__device__ __forceinline__ void suffix_select(
    const uint32_t* h, int G, int nbins, int rank,
    uint32_t* s_wtot, uint32_t* s_sel)
{
    const int t = threadIdx.x, lane = t & 31, warp = t >> 5;
    int v = 0;
    if (t * G < nbins) {
        #pragma unroll
        for (int j = 0; j < 8; j++)
            if (j < G) v += (int)h[t * G + j];
    }
    // warp inclusive suffix scan
    int s = v;
    #pragma unroll
    for (int d = 1; d < 32; d <<= 1) {
        int o = __shfl_down_sync(0xffffffffu, s, d);
        if (lane + d < 32) s += o;
    }
    if (lane == 0) s_wtot[warp] = (uint32_t)s;
    __syncthreads();
    if (warp == 0) {
        int wv = (lane < NWARPS) ? (int)s_wtot[lane] : 0;
        int ws = wv;
        #pragma unroll
        for (int d = 1; d < 32; d <<= 1) {
            int o = __shfl_down_sync(0xffffffffu, ws, d);
            if (lane + d < 32) ws += o;
        }
        if (lane < NWARPS) s_wtot[lane] = (uint32_t)(ws - wv);  // strictly-above-warp sum
    }
    __syncthreads();
    int S = s + (int)s_wtot[warp];   // suffix count incl. my group
    int above = S - v;               // count strictly above my group
    if (t * G < nbins && S >= rank && above < rank) {
        int cum = above;
        for (int j = G - 1; j >= 0; j--) {
            int c = (int)h[t * G + j];
            if (cum + c >= rank) {
                s_sel[0] = (uint32_t)(t * G + j);
                s_sel[1] = (uint32_t)(rank - cum);
                s_sel[2] = (uint32_t)c;
                break;
            }
            cum += c;
        }
    }
    __syncthreads();
}

__device__ __forceinline__ void clear_hist(uint32_t* h) {
    for (int i = threadIdx.x; i < HBINS; i += THREADS) h[i] = 0;
}

__global__ void __launch_bounds__(THREADS, 2)
topk_filter_kernel(const float* __restrict__ x, const int* __restrict__ kptr,
                   float* __restrict__ out)
{
    extern __shared__ uint32_t sm[];
    uint32_t* skeys  = sm;                      // NCOLS words
    uint32_t* h      = sm + NCOLS;              // HBINS words (L1 warp-hists / hist2 / hist3 / tie buf)
    uint32_t* s_wtot = h + HBINS;               // NWARPS
    uint32_t* s_sel  = s_wtot + NWARPS;         // 4
    uint32_t* s_var  = s_sel + 4;               // 4: [0]=counter, [1]=idx_cut, [2]=bsearch count

    const int row  = blockIdx.x;
    const int t    = threadIdx.x;
    const int lane = t & 31;
    const int warp = t >> 5;
    const int k    = *kptr;

    const float4* xin  = (const float4*)(x   + (size_t)row * NCOLS);
    float4*       xout = (float4*)      (out + (size_t)row * NCOLS);

    if (k >= NCOLS) {   // keep everything
        #pragma unroll 4
        for (int i = 0; i < EPT; i++) xout[i * THREADS + t] = __ldcs(&xin[i * THREADS + t]);
        return;
    }
    if (k <= 0) {       // keep nothing
        float4 z = make_float4(0.f, 0.f, 0.f, 0.f);
        #pragma unroll 4
        for (int i = 0; i < EPT; i++) xout[i * THREADS + t] = z;
        return;
    }

    // ---------------- P0: load + key transform + L1 per-warp 256-bin histogram (no atomics)
    clear_hist(h);
    __syncthreads();

    uint32_t* wh = h + (warp << 8);   // this warp's private 256-bin hist
    #pragma unroll 4
    for (int i = 0; i < EPT; i++) {
        float4 v = __ldcs(&xin[i * THREADS + t]);
        uint4 kk;
        kk.x = f2key(v.x); kk.y = f2key(v.y); kk.z = f2key(v.z); kk.w = f2key(v.w);
        ((uint4*)skeys)[i * THREADS + t] = kk;
        #pragma unroll
        for (int c = 0; c < 4; c++) {
            uint32_t key = (c == 0) ? kk.x : (c == 1) ? kk.y : (c == 2) ? kk.z : kk.w;
            uint32_t bin = key >> 24;
            unsigned mm = __match_any_sync(0xffffffffu, bin);
            if (lane == __ffs(mm) - 1) wh[bin] += (uint32_t)__popc(mm);
        }
    }
    __syncthreads();

    // reduce 16 warp-hists -> totals in h[0..255]
    uint32_t tot = 0;
    if (t < 256) {
        #pragma unroll
        for (int w = 0; w < NWARPS; w++) tot += h[(w << 8) + t];
    }
    __syncthreads();
    if (t < 256) h[t] = tot;
    __syncthreads();

    suffix_select(h, 1, 256, k, s_wtot, s_sel);
    const uint32_t b1 = s_sel[0];
    const int      k1 = (int)s_sel[1];

    // ---------------- P2: hist of key bits [23:12] among elements whose top 8 bits == b1
    clear_hist(h);
    __syncthreads();
    #pragma unroll 4
    for (int i = 0; i < EPT; i++) {
        uint4 kk = ((uint4*)skeys)[i * THREADS + t];
        if ((kk.x >> 24) == b1) atomicAdd(&h[(kk.x >> 12) & 0xFFFu], 1u);
        if ((kk.y >> 24) == b1) atomicAdd(&h[(kk.y >> 12) & 0xFFFu], 1u);
        if ((kk.z >> 24) == b1) atomicAdd(&h[(kk.z >> 12) & 0xFFFu], 1u);
        if ((kk.w >> 24) == b1) atomicAdd(&h[(kk.w >> 12) & 0xFFFu], 1u);
    }
    __syncthreads();

    suffix_select(h, 8, HBINS, k1, s_wtot, s_sel);
    const uint32_t prefix20 = (b1 << 12) | s_sel[0];
    const int      k2       = (int)s_sel[1];

    // ---------------- P3: hist of key bits [11:0] among elements whose top 20 bits match
    clear_hist(h);
    __syncthreads();
    #pragma unroll 4
    for (int i = 0; i < EPT; i++) {
        uint4 kk = ((uint4*)skeys)[i * THREADS + t];
        if ((kk.x >> 12) == prefix20) atomicAdd(&h[kk.x & 0xFFFu], 1u);
        if ((kk.y >> 12) == prefix20) atomicAdd(&h[kk.y & 0xFFFu], 1u);
        if ((kk.z >> 12) == prefix20) atomicAdd(&h[kk.z & 0xFFFu], 1u);
        if ((kk.w >> 12) == prefix20) atomicAdd(&h[kk.w & 0xFFFu], 1u);
    }
    __syncthreads();

    suffix_select(h, 8, HBINS, k2, s_wtot, s_sel);
    const uint32_t T    = (prefix20 << 12) | s_sel[0];  // exact threshold key (k-th largest)
    const int      m    = (int)s_sel[1];                // how many tied-at-T to keep
    const int      n_eq = (int)s_sel[2];                // how many are tied at T

    // ---------------- tie resolution: keep the m lowest-index elements equal to T
    uint32_t idx_cut = 0xFFFFFFFFu;   // n_eq == m: keep all ties (common case, pass skipped)
    if (n_eq != m) {
        if (t == 0) s_var[0] = 0;
        __syncthreads();
        uint16_t* tb = (uint16_t*)h;  // reuse hist region: 8192 u16 slots
        #pragma unroll 4
        for (int i = 0; i < EPT; i++) {
            uint4 kk = ((uint4*)skeys)[i * THREADS + t];
            int base = (i * THREADS + t) * 4;
            if (kk.x == T) { unsigned p = atomicAdd(&s_var[0], 1u); if (p < TIE_CAP) tb[p] = (uint16_t)(base);     }
            if (kk.y == T) { unsigned p = atomicAdd(&s_var[0], 1u); if (p < TIE_CAP) tb[p] = (uint16_t)(base + 1); }
            if (kk.z == T) { unsigned p = atomicAdd(&s_var[0], 1u); if (p < TIE_CAP) tb[p] = (uint16_t)(base + 2); }
            if (kk.w == T) { unsigned p = atomicAdd(&s_var[0], 1u); if (p < TIE_CAP) tb[p] = (uint16_t)(base + 3); }
        }
        __syncthreads();
        unsigned cnt = s_var[0];
        if (cnt <= TIE_CAP) {
            // pairwise rank (cnt is tiny in practice); indices are unique -> exactly one winner
            for (unsigned i = t; i < cnt; i += THREADS) {
                uint16_t my = tb[i];
                int c = 0;
                for (unsigned j = 0; j < cnt; j++) c += (tb[j] < my);
                if (c == m - 1) s_var[1] = (uint32_t)my;
            }
            __syncthreads();
            idx_cut = s_var[1];
        } else {
            // pathological fallback: counting binary search on index
            int lo = 0, hi = NCOLS - 1;
            while (lo < hi) {
                int mid = (lo + hi) >> 1;
                if (t == 0) s_var[2] = 0;
                __syncthreads();
                int local = 0;
                #pragma unroll 4
                for (int i = 0; i < EPT; i++) {
                    uint4 kk = ((uint4*)skeys)[i * THREADS + t];
                    int base = (i * THREADS + t) * 4;
                    local += (kk.x == T && base     <= mid);
                    local += (kk.y == T && base + 1 <= mid);
                    local += (kk.z == T && base + 2 <= mid);
                    local += (kk.w == T && base + 3 <= mid);
                }
                #pragma unroll
                for (int d = 16; d; d >>= 1) local += __shfl_down_sync(0xffffffffu, local, d);
                if (lane == 0 && local) atomicAdd(&s_var[2], (uint32_t)local);
                __syncthreads();
                if ((int)s_var[2] >= m) hi = mid; else lo = mid + 1;
                __syncthreads();
            }
            idx_cut = (uint32_t)lo;
        }
    }

    // ---------------- P5: output. keep iff key > T, or key == T with index <= idx_cut
    #pragma unroll 4
    for (int i = 0; i < EPT; i++) {
        uint4 kk = ((uint4*)skeys)[i * THREADS + t];
        uint32_t base = (uint32_t)(i * THREADS + t) * 4u;
        float4 o;
        o.x = (kk.x > T || (kk.x == T && base      <= idx_cut)) ? key2f(kk.x) : 0.0f;
        o.y = (kk.y > T || (kk.y == T && base + 1u <= idx_cut)) ? key2f(kk.y) : 0.0f;
        o.z = (kk.z > T || (kk.z == T && base + 2u <= idx_cut)) ? key2f(kk.z) : 0.0f;
        o.w = (kk.w > T || (kk.w == T && base + 3u <= idx_cut)) ? key2f(kk.w) : 0.0f;
        __stcs(&xout[i * THREADS + t], o);
    }
}

extern "C" void kernel_launch(void* const* d_in, const int* in_sizes, int n_in,
                              void* d_out, int out_size)
{
    // identify inputs: x is the big one, k the scalar
    int xi = 0, ki = 1;
    if (n_in >= 2 && in_sizes[1] > in_sizes[0]) { xi = 1; ki = 0; }

    const float* x  = (const float*)d_in[xi];
    const int*   kp = (const int*)  d_in[ki];
    float*       out = (float*)d_out;

    int nrows = in_sizes[xi] / NCOLS;

    cudaFuncSetAttribute(topk_filter_kernel,
                         cudaFuncAttributeMaxDynamicSharedMemorySize, SMEM_BYTES);
    topk_filter_kernel<<<nrows, THREADS, SMEM_BYTES>>>(x, kp, out);
}

// round 5
// speedup vs baseline: 1.2444x; 1.2444x over previous
#include <cuda_runtime.h>
#include <stdint.h>

#define NCOLS   24576
#define THREADS 512
#define NWARPS  (THREADS / 32)
#define EPT     (NCOLS / (THREADS * 4))   // 12 uint4 per thread
#define HWORDS  2048                       // 11-bit histogram region
#define CAP     1184                       // candidate capacity (inside h region)
// smem words: keys + hist + warp-totals(16) + select-out(4) + vars(8)
#define SMEM_WORDS (NCOLS + HWORDS + NWARPS + 4 + 8)
#define SMEM_BYTES (SMEM_WORDS * 4)

// ---- order-preserving float<->key transform (bigger key = bigger float)
__device__ __forceinline__ uint32_t f2key(float f) {
    uint32_t b = __float_as_uint(f);
    return (b & 0x80000000u) ? ~b : (b | 0x80000000u);
}
__device__ __forceinline__ float key2f(uint32_t k) {
    uint32_t b = (k & 0x80000000u) ? (k ^ 0x80000000u) : ~k;
    return __uint_as_float(b);
}

// Block-wide suffix select over histogram h: thread t owns bins [t*G, t*G+G).
// Finds bin b = max{b : count(bins >= b) >= rank}; writes s_sel[0]=bin,
// s_sel[1]=rank-within-bin (1-based), s_sel[2]=bin count.
__device__ __forceinline__ void suffix_select(
    const uint32_t* h, int G, int nbins, int rank,
    uint32_t* s_wtot, uint32_t* s_sel)
{
    const int t = threadIdx.x, lane = t & 31, warp = t >> 5;
    int v = 0;
    if (t * G < nbins) {
        #pragma unroll
        for (int j = 0; j < 8; j++)
            if (j < G) v += (int)h[t * G + j];
    }
    int s = v;
    #pragma unroll
    for (int d = 1; d < 32; d <<= 1) {
        int o = __shfl_down_sync(0xffffffffu, s, d);
        if (lane + d < 32) s += o;
    }
    if (lane == 0) s_wtot[warp] = (uint32_t)s;
    __syncthreads();
    if (warp == 0) {
        int wv = (lane < NWARPS) ? (int)s_wtot[lane] : 0;
        int ws = wv;
        #pragma unroll
        for (int d = 1; d < 32; d <<= 1) {
            int o = __shfl_down_sync(0xffffffffu, ws, d);
            if (lane + d < 32) ws += o;
        }
        if (lane < NWARPS) s_wtot[lane] = (uint32_t)(ws - wv);  // strictly-above-warp sum
    }
    __syncthreads();
    int S = s + (int)s_wtot[warp];
    int above = S - v;
    if (t * G < nbins && S >= rank && above < rank) {
        int cum = above;
        for (int j = G - 1; j >= 0; j--) {
            int c = (int)h[t * G + j];
            if (cum + c >= rank) {
                s_sel[0] = (uint32_t)(t * G + j);
                s_sel[1] = (uint32_t)(rank - cum);
                s_sel[2] = (uint32_t)c;
                break;
            }
            cum += c;
        }
    }
    __syncthreads();
}

__device__ __forceinline__ void clear_hist(uint32_t* h) {
    #pragma unroll
    for (int i = 0; i < HWORDS / THREADS; i++) h[i * THREADS + threadIdx.x] = 0;
}

// warp-aggregated candidate append (sweep loop is warp-uniform)
__device__ __forceinline__ void append(uint32_t key, int idx, uint32_t Tfloor,
                                       uint32_t* ckey, uint16_t* cidx, uint32_t* ctr)
{
    bool p = key >= Tfloor;
    unsigned m = __ballot_sync(0xffffffffu, p);
    if (m == 0) return;
    int lane = threadIdx.x & 31;
    int leader = __ffs(m) - 1;
    unsigned base = 0;
    if (lane == leader) base = atomicAdd(ctr, (uint32_t)__popc(m));
    base = __shfl_sync(0xffffffffu, base, leader);
    if (p) {
        unsigned pos = base + __popc(m & ((1u << lane) - 1u));
        if (pos < CAP) { ckey[pos] = key; cidx[pos] = (uint16_t)idx; }
    }
}

__global__ void __launch_bounds__(THREADS, 2)
topk_filter_kernel(const float* __restrict__ x, const int* __restrict__ kptr,
                   float* __restrict__ out)
{
    extern __shared__ uint32_t sm[];
    uint32_t* skeys  = sm;                      // NCOLS words
    uint32_t* h      = sm + NCOLS;              // HWORDS words
    uint32_t* s_wtot = h + HWORDS;              // NWARPS
    uint32_t* s_sel  = s_wtot + NWARPS;         // 4
    uint32_t* s_var  = s_sel + 4;               // 8: [0]=cand ctr, [1]=cut lo, [2]=cut hi, [3]=bsearch ctr
    // candidate arrays live inside h (used only after maxes-select is done)
    uint32_t* ckey = h + 256;
    uint16_t* cidx = (uint16_t*)(ckey + CAP);   // 256 + 1184 + 592 = 2032 <= 2048 words

    const int t    = threadIdx.x;
    const int lane = t & 31;
    const int k    = *kptr;

    const float4* xin  = (const float4*)(x   + (size_t)blockIdx.x * NCOLS);
    float4*       xout = (float4*)      (out + (size_t)blockIdx.x * NCOLS);

    if (k >= NCOLS) {
        #pragma unroll 4
        for (int i = 0; i < EPT; i++) xout[i * THREADS + t] = __ldcs(&xin[i * THREADS + t]);
        return;
    }
    if (k <= 0) {
        float4 z = make_float4(0.f, 0.f, 0.f, 0.f);
        #pragma unroll 4
        for (int i = 0; i < EPT; i++) xout[i * THREADS + t] = z;
        return;
    }

    bool fb = (k > THREADS);   // sampled-threshold guarantee needs k <= 512

    // ---------------- P0: load + key transform + per-thread max ----------------
    if (t == 0) s_var[0] = 0;
    clear_hist(h);
    uint32_t mymax = 0;
    #pragma unroll 4
    for (int i = 0; i < EPT; i++) {
        float4 v = __ldcs(&xin[i * THREADS + t]);
        uint4 kk;
        kk.x = f2key(v.x); kk.y = f2key(v.y); kk.z = f2key(v.z); kk.w = f2key(v.w);
        ((uint4*)skeys)[i * THREADS + t] = kk;
        uint32_t m0 = max(kk.x, kk.y), m1 = max(kk.z, kk.w);
        mymax = max(mymax, max(m0, m1));
    }
    __syncthreads();

    uint32_t Tkey = 0, idx_cut = 0xFFFFFFFFu;

    if (!fb) {
        // ------------- maxes histogram (11-bit bins), aggregated atomics -------------
        uint32_t bin = mymax >> 21;
        unsigned mm = __match_any_sync(0xffffffffu, bin);
        if (lane == __ffs(mm) - 1) atomicAdd(&h[bin], (uint32_t)__popc(mm));
        __syncthreads();

        // k-th largest thread-max lives in/above this bin => count(>= bin<<21) >= k
        suffix_select(h, 4, HWORDS, k, s_wtot, s_sel);
        const uint32_t Tfloor = s_sel[0] << 21;

        // ------------- compaction sweep: collect all keys >= Tfloor -------------
        #pragma unroll 4
        for (int i = 0; i < EPT; i++) {
            uint4 kk = ((uint4*)skeys)[i * THREADS + t];
            int base = (i * THREADS + t) * 4;
            append(kk.x, base,     Tfloor, ckey, cidx, &s_var[0]);
            append(kk.y, base + 1, Tfloor, ckey, cidx, &s_var[0]);
            append(kk.z, base + 2, Tfloor, ckey, cidx, &s_var[0]);
            append(kk.w, base + 3, Tfloor, ckey, cidx, &s_var[0]);
        }
        __syncthreads();
        const unsigned n = s_var[0];

        if (n > CAP) {
            fb = true;
        } else {
            // ------------- exact k-th by composite (key desc, idx asc): rank count -------------
            // ck48 = (key << 16) | (0xFFFF - idx); all distinct. n >= k guaranteed.
            for (unsigned i = t; i < n; i += THREADS) {
                unsigned long long cki =
                    ((unsigned long long)ckey[i] << 16) | (unsigned long long)(0xFFFFu - cidx[i]);
                int c = 0;
                for (unsigned j = 0; j < n; j++) {
                    unsigned long long ckj =
                        ((unsigned long long)ckey[j] << 16) | (unsigned long long)(0xFFFFu - cidx[j]);
                    c += (ckj > cki);
                }
                if (c == k - 1) {   // exactly one winner
                    s_var[1] = (uint32_t)(cki & 0xFFFFFFFFu);
                    s_var[2] = (uint32_t)(cki >> 32);
                }
            }
            __syncthreads();
            unsigned long long cut =
                ((unsigned long long)s_var[2] << 32) | (unsigned long long)s_var[1];
            Tkey    = (uint32_t)(cut >> 16);
            idx_cut = 0xFFFFu - (uint32_t)(cut & 0xFFFFu);
        }
    }

    // ---------------- FALLBACK: full 3-pass radix select (pathological inputs) ----------------
    if (fb) {
        __syncthreads();
        // pass 1: key bits [31:21]
        clear_hist(h);
        __syncthreads();
        #pragma unroll 4
        for (int i = 0; i < EPT; i++) {
            uint4 kk = ((uint4*)skeys)[i * THREADS + t];
            atomicAdd(&h[kk.x >> 21], 1u);
            atomicAdd(&h[kk.y >> 21], 1u);
            atomicAdd(&h[kk.z >> 21], 1u);
            atomicAdd(&h[kk.w >> 21], 1u);
        }
        __syncthreads();
        suffix_select(h, 4, 2048, k, s_wtot, s_sel);
        const uint32_t b1 = s_sel[0];
        const int      k1 = (int)s_sel[1];

        // pass 2: key bits [20:10] among prefix matches
        clear_hist(h);
        __syncthreads();
        #pragma unroll 4
        for (int i = 0; i < EPT; i++) {
            uint4 kk = ((uint4*)skeys)[i * THREADS + t];
            if ((kk.x >> 21) == b1) atomicAdd(&h[(kk.x >> 10) & 0x7FFu], 1u);
            if ((kk.y >> 21) == b1) atomicAdd(&h[(kk.y >> 10) & 0x7FFu], 1u);
            if ((kk.z >> 21) == b1) atomicAdd(&h[(kk.z >> 10) & 0x7FFu], 1u);
            if ((kk.w >> 21) == b1) atomicAdd(&h[(kk.w >> 10) & 0x7FFu], 1u);
        }
        __syncthreads();
        suffix_select(h, 4, 2048, k1, s_wtot, s_sel);
        const uint32_t prefix22 = (b1 << 11) | s_sel[0];
        const int      k2       = (int)s_sel[1];

        // pass 3: key bits [9:0]
        clear_hist(h);
        __syncthreads();
        #pragma unroll 4
        for (int i = 0; i < EPT; i++) {
            uint4 kk = ((uint4*)skeys)[i * THREADS + t];
            if ((kk.x >> 10) == prefix22) atomicAdd(&h[kk.x & 0x3FFu], 1u);
            if ((kk.y >> 10) == prefix22) atomicAdd(&h[kk.y & 0x3FFu], 1u);
            if ((kk.z >> 10) == prefix22) atomicAdd(&h[kk.z & 0x3FFu], 1u);
            if ((kk.w >> 10) == prefix22) atomicAdd(&h[kk.w & 0x3FFu], 1u);
        }
        __syncthreads();
        suffix_select(h, 2, 1024, k2, s_wtot, s_sel);
        Tkey = (prefix22 << 10) | s_sel[0];
        const int m    = (int)s_sel[1];
        const int n_eq = (int)s_sel[2];

        idx_cut = 0xFFFFFFFFu;
        if (n_eq != m) {
            // counting binary search on index for the tie cut
            int lo = 0, hi = NCOLS - 1;
            while (lo < hi) {
                int mid = (lo + hi) >> 1;
                if (t == 0) s_var[3] = 0;
                __syncthreads();
                int local = 0;
                #pragma unroll 4
                for (int i = 0; i < EPT; i++) {
                    uint4 kk = ((uint4*)skeys)[i * THREADS + t];
                    int base = (i * THREADS + t) * 4;
                    local += (kk.x == Tkey && base     <= mid);
                    local += (kk.y == Tkey && base + 1 <= mid);
                    local += (kk.z == Tkey && base + 2 <= mid);
                    local += (kk.w == Tkey && base + 3 <= mid);
                }
                #pragma unroll
                for (int d = 16; d; d >>= 1) local += __shfl_down_sync(0xffffffffu, local, d);
                if (lane == 0 && local) atomicAdd(&s_var[3], (uint32_t)local);
                __syncthreads();
                if ((int)s_var[3] >= m) hi = mid; else lo = mid + 1;
                __syncthreads();
            }
            idx_cut = (uint32_t)lo;
        }
    }

    // ---------------- P5: output. keep iff key > T, or key == T with index <= idx_cut ----------------
    #pragma unroll 4
    for (int i = 0; i < EPT; i++) {
        uint4 kk = ((uint4*)skeys)[i * THREADS + t];
        uint32_t base = (uint32_t)(i * THREADS + t) * 4u;
        float4 o;
        o.x = (kk.x > Tkey || (kk.x == Tkey && base      <= idx_cut)) ? key2f(kk.x) : 0.0f;
        o.y = (kk.y > Tkey || (kk.y == Tkey && base + 1u <= idx_cut)) ? key2f(kk.y) : 0.0f;
        o.z = (kk.z > Tkey || (kk.z == Tkey && base + 2u <= idx_cut)) ? key2f(kk.z) : 0.0f;
        o.w = (kk.w > Tkey || (kk.w == Tkey && base + 3u <= idx_cut)) ? key2f(kk.w) : 0.0f;
        __stcs(&xout[i * THREADS + t], o);
    }
}

extern "C" void kernel_launch(void* const* d_in, const int* in_sizes, int n_in,
                              void* d_out, int out_size)
{
    int xi = 0, ki = 1;
    if (n_in >= 2 && in_sizes[1] > in_sizes[0]) { xi = 1; ki = 0; }

    const float* x  = (const float*)d_in[xi];
    const int*   kp = (const int*)  d_in[ki];
    float*       out = (float*)d_out;

    int nrows = in_sizes[xi] / NCOLS;

    cudaFuncSetAttribute(topk_filter_kernel,
                         cudaFuncAttributeMaxDynamicSharedMemorySize, SMEM_BYTES);
    topk_filter_kernel<<<nrows, THREADS, SMEM_BYTES>>>(x, kp, out);
}